// round 16
// baseline (speedup 1.0000x reference)
#include <cuda_runtime.h>
#include <cuda_bf16.h>
#include <math.h>
#include <cstdint>

// Problem constants
#define B_  2
#define N_  2048
#define D_  1024
#define H_  16
#define DH_ 64
#define ROWS_ (B_*N_)          // 4096
#define BHN_  (B_*H_*N_)       // 65536

// ---------------------------------------------------------------------------
// MUFU approx helpers
// ---------------------------------------------------------------------------
__device__ __forceinline__ float sqrt_apx(float x) {
    float r; asm("sqrt.approx.f32 %0, %1;" : "=f"(r) : "f"(x)); return r;
}
__device__ __forceinline__ float lg2_apx(float x) {
    float r; asm("lg2.approx.f32 %0, %1;" : "=f"(r) : "f"(x)); return r;
}
__device__ __forceinline__ float ex2_apx(float x) {
    float r; asm("ex2.approx.f32 %0, %1;" : "=f"(r) : "f"(x)); return r;
}

// ---------------------------------------------------------------------------
// ldmatrix / mma.sync / cp.async helpers (baseline PTX)
// ---------------------------------------------------------------------------
__device__ __forceinline__ uint32_t smem_u32(const void* p) {
    uint32_t a;
    asm("{ .reg .u64 t; cvta.to.shared.u64 t, %1; cvt.u32.u64 %0, t; }" : "=r"(a) : "l"(p));
    return a;
}
#define LDSM_X4(r, addr) \
    asm volatile("ldmatrix.sync.aligned.m8n8.x4.shared.b16 {%0,%1,%2,%3}, [%4];" \
        : "=r"((r)[0]), "=r"((r)[1]), "=r"((r)[2]), "=r"((r)[3]) : "r"(addr))
#define LDSM_X4T(r, addr) \
    asm volatile("ldmatrix.sync.aligned.m8n8.x4.trans.shared.b16 {%0,%1,%2,%3}, [%4];" \
        : "=r"((r)[0]), "=r"((r)[1]), "=r"((r)[2]), "=r"((r)[3]) : "r"(addr))
#define MMA_BF16(d, a, b0v, b1v) \
    asm volatile("mma.sync.aligned.m16n8k16.row.col.f32.bf16.bf16.f32 " \
        "{%0,%1,%2,%3}, {%4,%5,%6,%7}, {%8,%9}, {%0,%1,%2,%3};" \
        : "+f"((d)[0]), "+f"((d)[1]), "+f"((d)[2]), "+f"((d)[3]) \
        : "r"((a)[0]), "r"((a)[1]), "r"((a)[2]), "r"((a)[3]), "r"(b0v), "r"(b1v))
#define CVTPK(d, p0, p1) \
    asm("cvt.rn.bf16x2.f32 %0, %1, %2;" : "=r"(d) : "f"(p1), "f"(p0))
#define CPA16(sm, gp) \
    asm volatile("cp.async.cg.shared.global [%0], [%1], 16;" :: "r"(sm), "l"(gp) : "memory")
#define CPA_COMMIT() asm volatile("cp.async.commit_group;" ::: "memory")
#define CPA_WAIT(n)  asm volatile("cp.async.wait_group %0;" :: "n"(n) : "memory")

// ---------------------------------------------------------------------------
// Scratch (static device globals — no allocation)
// ---------------------------------------------------------------------------
__device__ float g_q[BHN_*DH_];
__device__ float g_k[BHN_*DH_];
__device__ float g_v[BHN_*DH_];
__device__ float g_kn[BHN_];
__device__ float g_qn[BHN_];
__device__ __nv_bfloat16 g_xh[ROWS_*D_],  g_xl[ROWS_*D_];
__device__ __nv_bfloat16 g_wqh[D_*D_], g_wql[D_*D_];
__device__ __nv_bfloat16 g_wkh[D_*D_], g_wkl[D_*D_];
__device__ __nv_bfloat16 g_wvh[D_*D_], g_wvl[D_*D_];
__device__ __nv_bfloat16 g_woh[D_*D_], g_wol[D_*D_];
__device__ __nv_bfloat16 g_cth[ROWS_*D_], g_ctl[ROWS_*D_];
__device__ __nv_bfloat16 g_qh[BHN_*DH_], g_ql[BHN_*DH_];
__device__ __nv_bfloat16 g_kh[BHN_*DH_], g_kl[BHN_*DH_];
__device__ __nv_bfloat16 g_vh[BHN_*DH_], g_vl[BHN_*DH_];

__device__ __forceinline__ float softplusf(float x) {
    return (x > 20.f) ? x : log1pf(__expf(x));
}

// ---------------------------------------------------------------------------
// fp32 -> (bf16 hi, bf16 lo) split, 4 elements/thread (inputs/weights only)
// ---------------------------------------------------------------------------
__global__ void split_bf16(const float* __restrict__ s,
                           __nv_bfloat16* __restrict__ h,
                           __nv_bfloat16* __restrict__ l, int n4)
{
    int i = blockIdx.x * blockDim.x + threadIdx.x;
    if (i >= n4) return;
    float4 v = ((const float4*)s)[i];
    __nv_bfloat16 h0 = __float2bfloat16(v.x), h1 = __float2bfloat16(v.y);
    __nv_bfloat16 h2 = __float2bfloat16(v.z), h3 = __float2bfloat16(v.w);
    __nv_bfloat16 l0 = __float2bfloat16(v.x - __bfloat162float(h0));
    __nv_bfloat16 l1 = __float2bfloat16(v.y - __bfloat162float(h1));
    __nv_bfloat16 l2 = __float2bfloat16(v.z - __bfloat162float(h2));
    __nv_bfloat16 l3 = __float2bfloat16(v.w - __bfloat162float(h3));
    ushort4 hv = make_ushort4(__bfloat16_as_ushort(h0), __bfloat16_as_ushort(h1),
                              __bfloat16_as_ushort(h2), __bfloat16_as_ushort(h3));
    ushort4 lv = make_ushort4(__bfloat16_as_ushort(l0), __bfloat16_as_ushort(l1),
                              __bfloat16_as_ushort(l2), __bfloat16_as_ushort(l3));
    ((ushort4*)h)[i] = hv;
    ((ushort4*)l)[i] = lv;
}

// ---------------------------------------------------------------------------
// bf16-split HMMA GEMM, cp.async 2-stage pipeline, fused hi/lo split epilogue.
// (unchanged from R14 — passed at 721us)
// ---------------------------------------------------------------------------
#define GS_AH 0
#define GS_AL 10240
#define GS_BH 20480
#define GS_BL 25600
#define GS_STG 30720
#define GEMM_SMEM (2*GS_STG)   // 61440

#define GFILL(kk, bufo) do { \
    _Pragma("unroll") \
    for (int ii = 0; ii < 2; ii++) { \
        int idx = tid + ii * 256; int rr = idx >> 2, cch = idx & 3; \
        size_t g = (size_t)(rowBase + rr) * D_ + (kk) + cch * 8; \
        CPA16(sb + (bufo) + GS_AH + rr * 80 + cch * 16, Ah + g); \
        CPA16(sb + (bufo) + GS_AL + rr * 80 + cch * 16, Al + g); \
    } \
    { int rr = tid >> 2, cch = tid & 3; \
      size_t g = (size_t)(colBase + rr) * D_ + (kk) + cch * 8; \
      CPA16(sb + (bufo) + GS_BH + rr * 80 + cch * 16, Bh + g); \
      CPA16(sb + (bufo) + GS_BL + rr * 80 + cch * 16, Bl + g); } \
} while (0)

__global__ __launch_bounds__(256)
void gemm_tc(const __nv_bfloat16* __restrict__ Ah, const __nv_bfloat16* __restrict__ Al,
             const __nv_bfloat16* __restrict__ Bh0, const __nv_bfloat16* __restrict__ Bl0,
             const __nv_bfloat16* __restrict__ Bh1, const __nv_bfloat16* __restrict__ Bl1,
             const __nv_bfloat16* __restrict__ Bh2, const __nv_bfloat16* __restrict__ Bl2,
             float* __restrict__ C0, float* __restrict__ C1, float* __restrict__ C2,
             __nv_bfloat16* __restrict__ H0, __nv_bfloat16* __restrict__ L0,
             __nv_bfloat16* __restrict__ H1, __nv_bfloat16* __restrict__ L1,
             __nv_bfloat16* __restrict__ H2, __nv_bfloat16* __restrict__ L2,
             int headLayout)
{
    extern __shared__ char gsm[];
    const uint32_t sb = smem_u32(gsm);

    const int z = blockIdx.z;
    const __nv_bfloat16* __restrict__ Bh = (z == 0) ? Bh0 : (z == 1) ? Bh1 : Bh2;
    const __nv_bfloat16* __restrict__ Bl = (z == 0) ? Bl0 : (z == 1) ? Bl1 : Bl2;
    float* __restrict__ C = (z == 0) ? C0 : (z == 1) ? C1 : C2;
    __nv_bfloat16* __restrict__ Hd = (z == 0) ? H0 : (z == 1) ? H1 : H2;
    __nv_bfloat16* __restrict__ Ld = (z == 0) ? L0 : (z == 1) ? L1 : L2;

    const int tid  = threadIdx.x;
    const int lane = tid & 31;
    const int wid  = tid >> 5;
    const int wm   = wid & 3;
    const int wn   = wid >> 2;
    const int rowBase = blockIdx.y * 128;
    const int colBase = blockIdx.x * 64;

    const uint32_t aBase = (uint32_t)((wm * 32 + (lane & 15)) * 80 + (lane >> 4) * 16);
    const uint32_t bBase = (uint32_t)((wn * 32 + ((lane >> 4) & 1) * 8 + (lane & 7)) * 80
                                      + ((lane >> 3) & 1) * 16);

    float acc[2][4][4];
#pragma unroll
    for (int mf = 0; mf < 2; mf++)
#pragma unroll
        for (int nf = 0; nf < 4; nf++)
#pragma unroll
            for (int r = 0; r < 4; r++) acc[mf][nf][r] = 0.f;

    GFILL(0, 0);
    CPA_COMMIT();

    for (int kt = 0; kt < 32; kt++) {
        const uint32_t base = sb + (uint32_t)((kt & 1) * GS_STG);
        if (kt + 1 < 32) {
            GFILL((kt + 1) * 32, ((kt + 1) & 1) * GS_STG);
            CPA_COMMIT();
            CPA_WAIT(1);
        } else {
            CPA_WAIT(0);
        }
        __syncthreads();

#pragma unroll
        for (int k16 = 0; k16 < 2; k16++) {
            uint32_t ah[2][4], al[2][4], bh[2][4], bl[2][4];
#pragma unroll
            for (int mf = 0; mf < 2; mf++) {
                LDSM_X4(ah[mf], base + GS_AH + aBase + mf * 1280 + k16 * 32);
                LDSM_X4(al[mf], base + GS_AL + aBase + mf * 1280 + k16 * 32);
            }
#pragma unroll
            for (int n16 = 0; n16 < 2; n16++) {
                LDSM_X4(bh[n16], base + GS_BH + bBase + n16 * 1280 + k16 * 32);
                LDSM_X4(bl[n16], base + GS_BL + bBase + n16 * 1280 + k16 * 32);
            }
#pragma unroll
            for (int mf = 0; mf < 2; mf++)
#pragma unroll
                for (int nf = 0; nf < 4; nf++) {
                    const int n16 = nf >> 1, pr = (nf & 1) * 2;
                    MMA_BF16(acc[mf][nf], ah[mf], bh[n16][pr], bh[n16][pr + 1]);
                    MMA_BF16(acc[mf][nf], ah[mf], bl[n16][pr], bl[n16][pr + 1]);
                    MMA_BF16(acc[mf][nf], al[mf], bh[n16][pr], bh[n16][pr + 1]);
                }
        }
        __syncthreads();
    }

    const int gi = lane >> 2, t4 = lane & 3;
#pragma unroll
    for (int mf = 0; mf < 2; mf++) {
#pragma unroll
        for (int nf = 0; nf < 4; nf++) {
            int col = colBase + wn * 32 + nf * 8 + t4 * 2;
            int row0 = rowBase + wm * 32 + mf * 16 + gi;
            int row1 = row0 + 8;
            size_t off0, off1;
            if (headLayout) {
                int h = col >> 6, dh = col & 63;
                int b0 = row0 >> 11, n0 = row0 & 2047;
                int b1 = row1 >> 11, n1 = row1 & 2047;
                off0 = (((size_t)(b0 * H_ + h)) * N_ + n0) * DH_ + dh;
                off1 = (((size_t)(b1 * H_ + h)) * N_ + n1) * DH_ + dh;
            } else {
                off0 = (size_t)row0 * D_ + col;
                off1 = (size_t)row1 * D_ + col;
            }
            float2 v01 = make_float2(acc[mf][nf][0], acc[mf][nf][1]);
            float2 v23 = make_float2(acc[mf][nf][2], acc[mf][nf][3]);
            *(float2*)(C + off0) = v01;
            *(float2*)(C + off1) = v23;
            if (Hd) {
                uint32_t hp0; CVTPK(hp0, v01.x, v01.y);
                float lx = v01.x - __uint_as_float(hp0 << 16);
                float ly = v01.y - __uint_as_float(hp0 & 0xFFFF0000u);
                uint32_t lp0; CVTPK(lp0, lx, ly);
                *(uint32_t*)(Hd + off0) = hp0;
                *(uint32_t*)(Ld + off0) = lp0;
                uint32_t hp1; CVTPK(hp1, v23.x, v23.y);
                lx = v23.x - __uint_as_float(hp1 << 16);
                ly = v23.y - __uint_as_float(hp1 & 0xFFFF0000u);
                uint32_t lp1; CVTPK(lp1, lx, ly);
                *(uint32_t*)(Hd + off1) = hp1;
                *(uint32_t*)(Ld + off1) = lp1;
            }
        }
    }
}

// ---------------------------------------------------------------------------
// Row squared-norms: one warp per 64-elem row.
// ---------------------------------------------------------------------------
__global__ void row_norms(const float* __restrict__ src, float* __restrict__ dst)
{
    int gw = (blockIdx.x * blockDim.x + threadIdx.x) >> 5;
    int lane = threadIdx.x & 31;
    if (gw >= BHN_) return;
    const float* r = src + (size_t)gw * DH_;
    float a = r[lane], b = r[lane + 32];
    float s = a * a + b * b;
#pragma unroll
    for (int off = 16; off > 0; off >>= 1)
        s += __shfl_xor_sync(0xFFFFFFFFu, s, off);
    if (lane == 0) dst[gw] = s;
}

// ---------------------------------------------------------------------------
// Tensor-core hyperbolic flash attention, 128-row q-tile (8 warps).
// Fast-path score transform: arg>4 (ed>2) => asy branch, 2 MUFUs.
// ---------------------------------------------------------------------------
#define AST 144        // bytes per smem row
#define SQH 0
#define SQL (SQH + 128*AST)
#define SKH (SQL + 128*AST)
#define SKL (SKH + 64*AST)
#define SVH (SKL + 64*AST)     // straight V: rows=key, cols=dh
#define SVL (SVH + 64*AST)
#define SKN (SVL + 64*AST)
#define ATT_SMEM (SKN + 256)   // 73984 B

__global__ __launch_bounds__(256)
void hyp_attn_mma(const __nv_bfloat16* __restrict__ qh, const __nv_bfloat16* __restrict__ ql,
                  const __nv_bfloat16* __restrict__ kh, const __nv_bfloat16* __restrict__ kl,
                  const __nv_bfloat16* __restrict__ vh, const __nv_bfloat16* __restrict__ vl,
                  const float* __restrict__ qn_, const float* __restrict__ kn_,
                  __nv_bfloat16* __restrict__ cth, __nv_bfloat16* __restrict__ ctl,
                  const float* __restrict__ logc_p, const float* __restrict__ logb_p)
{
    extern __shared__ char smem[];
    const uint32_t sb = smem_u32(smem);
    const int tid = threadIdx.x;
    const int lane = tid & 31;
    const int w = tid >> 5;                  // 0..7, m16 slab
    const int gi = lane >> 2, t4 = lane & 3;

    const int bh = blockIdx.y;
    const int qb = (gridDim.x - 1) - blockIdx.x;    // heavy blocks first
    const int r0 = qb * 128;

    const float c     = softplusf(*logc_p);
    const float beta2 = (softplusf(*logb_p) + 0.5f) * 1.44269504f;
    // asy-branch constants: p = ex2(b0 + b1*lg2(arg) + bc*ns)
    const float ab0 = -beta2 * 0.693f;
    const float ab1 = -beta2 * 0.34657359f;   // -beta2 * 0.5*ln2
    const float abc = -beta2 * 0.25f * c;

    // --- Q tile (hi/lo): 128 rows ---
    for (int i = tid; i < 1024; i += 256) {
        int r = i >> 3, ch = i & 7;
        size_t g = ((size_t)bh * N_ + r0 + r) * DH_ + ch * 8;
        *(uint4*)(smem + SQH + r * AST + ch * 16) = *(const uint4*)(qh + g);
        *(uint4*)(smem + SQL + r * AST + ch * 16) = *(const uint4*)(ql + g);
    }
    __syncthreads();

    const uint32_t aOff = (uint32_t)((w * 16 + (lane & 15)) * AST + (lane >> 4) * 16);
    uint32_t qfh[4][4], qfl[4][4];
#pragma unroll
    for (int s = 0; s < 4; s++) {
        LDSM_X4(qfh[s], sb + SQH + aOff + s * 32);
        LDSM_X4(qfl[s], sb + SQL + aOff + s * 32);
    }

    const float qn0 = qn_[bh * N_ + r0 + w * 16 + gi];
    const float qn1 = qn_[bh * N_ + r0 + w * 16 + gi + 8];

    float oacc[8][4];
#pragma unroll
    for (int f = 0; f < 8; f++)
#pragma unroll
        for (int r = 0; r < 4; r++) oacc[f][r] = 0.f;
    float l0 = 0.f, l1 = 0.f;

    const uint32_t bOffBase = (uint32_t)((((lane >> 4) & 1) * 8 + (lane & 7)) * AST
                                         + ((lane >> 3) & 1) * 16);
    const uint32_t vOffBase = (uint32_t)((lane & 15) * AST + (lane >> 4) * 16);

    const int ntiles = 2 * qb + 2;
    for (int T = 0; T < ntiles; T++) {
        __syncthreads();
        for (int i = tid; i < 512; i += 256) {
            int r = i >> 3, ch = i & 7;
            size_t g = ((size_t)bh * N_ + T * 64 + r) * DH_ + ch * 8;
            *(uint4*)(smem + SKH + r * AST + ch * 16) = *(const uint4*)(kh + g);
            *(uint4*)(smem + SKL + r * AST + ch * 16) = *(const uint4*)(kl + g);
            *(uint4*)(smem + SVH + r * AST + ch * 16) = *(const uint4*)(vh + g);
            *(uint4*)(smem + SVL + r * AST + ch * 16) = *(const uint4*)(vl + g);
        }
        if (tid < 64) *(float*)(smem + SKN + tid * 4) = kn_[bh * N_ + T * 64 + tid];
        __syncthreads();

        // --- S = Q·K^T (3-product split) ---
        float sacc[8][4];
#pragma unroll
        for (int f = 0; f < 8; f++)
#pragma unroll
            for (int r = 0; r < 4; r++) sacc[f][r] = 0.f;

#pragma unroll
        for (int s = 0; s < 4; s++) {
#pragma unroll
            for (int n16 = 0; n16 < 4; n16++) {
                uint32_t kbh[4], kbl[4];
                uint32_t bo = bOffBase + (uint32_t)(n16 * 16 * AST) + s * 32;
                LDSM_X4(kbh, sb + SKH + bo);
                LDSM_X4(kbl, sb + SKL + bo);
#pragma unroll
                for (int half = 0; half < 2; half++) {
                    const int nf = n16 * 2 + half, pr = half * 2;
                    MMA_BF16(sacc[nf], qfh[s], kbh[pr], kbh[pr + 1]);
                    MMA_BF16(sacc[nf], qfh[s], kbl[pr], kbl[pr + 1]);
                    MMA_BF16(sacc[nf], qfl[s], kbh[pr], kbh[pr + 1]);
                }
            }
        }

        // --- score transform: fast asy path (arg>4 <=> ed>2), 2 MUFUs ---
        const bool domask = (T >= 2 * qb);
#pragma unroll
        for (int f = 0; f < 8; f++) {
#pragma unroll
            for (int r = 0; r < 4; r++) {
                const int col = f * 8 + 2 * t4 + (r & 1);
                const int rl  = (r >> 1) ? (gi + 8) : gi;
                const float qnv = (r >> 1) ? qn1 : qn0;
                const float kn  = *(const float*)(smem + SKN + col * 4);
                const float ns  = qnv + kn;
                float diff = fmaxf(fmaf(sacc[f][r], -2.f, ns), 0.f);
                float arg  = diff + 1e-8f;
                float p;
                if (arg > 4.f) {
                    float lg = lg2_apx(arg);
                    p = ex2_apx(fmaf(ab1, lg, fmaf(abc, ns, ab0)));
                } else {
                    float ed  = sqrt_apx(arg);
                    float cns = c * ns;
                    float d_std = sqrt_apx(arg * (1.f + cns));
                    float tt2 = fmaf(0.125f * cns, cns, fmaf(0.5f, cns, 1.f));
                    float dist = (ed < 0.1f) ? (ed * tt2) : d_std;
                    p = ex2_apx(-beta2 * dist);
                }
                if (domask && (T * 64 + col > r0 + w * 16 + rl)) p = 0.f;
                if (r >> 1) l1 += p; else l0 += p;
                sacc[f][r] = p;
            }
        }

        // --- PV: repack P (split) to A-fragments; B = V via trans ldmatrix ---
#pragma unroll
        for (int s = 0; s < 4; s++) {
            uint32_t pah[4], pal[4];
            {
                const float* e = sacc[2 * s];
                const float* o = sacc[2 * s + 1];
                float pv[8] = { e[0], e[1], e[2], e[3], o[0], o[1], o[2], o[3] };
#pragma unroll
                for (int j = 0; j < 4; j++) {
                    uint32_t hpk; CVTPK(hpk, pv[2 * j], pv[2 * j + 1]);
                    pah[j] = hpk;
                    float f0 = pv[2 * j]     - __uint_as_float(hpk << 16);
                    float f1 = pv[2 * j + 1] - __uint_as_float(hpk & 0xFFFF0000u);
                    uint32_t lpk; CVTPK(lpk, f0, f1);
                    pal[j] = lpk;
                }
            }
#pragma unroll
            for (int n16 = 0; n16 < 4; n16++) {
                uint32_t vbh[4], vbl[4];
                uint32_t vo = vOffBase + (uint32_t)(s * 16 * AST) + n16 * 32;
                LDSM_X4T(vbh, sb + SVH + vo);
                LDSM_X4T(vbl, sb + SVL + vo);
#pragma unroll
                for (int half = 0; half < 2; half++) {
                    const int nf = n16 * 2 + half, pr = half * 2;
                    MMA_BF16(oacc[nf], pah, vbh[pr], vbh[pr + 1]);
                    MMA_BF16(oacc[nf], pah, vbl[pr], vbl[pr + 1]);
                    MMA_BF16(oacc[nf], pal, vbh[pr], vbh[pr + 1]);
                }
            }
        }
    }

    // --- reduce l across the 4 lanes sharing a row ---
    l0 += __shfl_xor_sync(0xFFFFFFFFu, l0, 1);
    l0 += __shfl_xor_sync(0xFFFFFFFFu, l0, 2);
    l1 += __shfl_xor_sync(0xFFFFFFFFu, l1, 1);
    l1 += __shfl_xor_sync(0xFFFFFFFFu, l1, 2);
    const float inv0 = 1.f / l0, inv1 = 1.f / l1;

    // --- store ctx hi/lo bf16 ---
    const int b = bh >> 4, h = bh & 15;
    const int row0 = r0 + w * 16 + gi;
    const int row1 = row0 + 8;
    const size_t o0 = ((size_t)b * N_ + row0) * D_ + h * DH_;
    const size_t o1 = ((size_t)b * N_ + row1) * D_ + h * DH_;
#pragma unroll
    for (int f = 0; f < 8; f++) {
        int col = f * 8 + 2 * t4;
        float a0 = oacc[f][0] * inv0, a1 = oacc[f][1] * inv0;
        uint32_t hp0; CVTPK(hp0, a0, a1);
        float lx = a0 - __uint_as_float(hp0 << 16);
        float ly = a1 - __uint_as_float(hp0 & 0xFFFF0000u);
        uint32_t lp0; CVTPK(lp0, lx, ly);
        *(uint32_t*)(cth + o0 + col) = hp0;
        *(uint32_t*)(ctl + o0 + col) = lp0;
        float b0v = oacc[f][2] * inv1, b1v = oacc[f][3] * inv1;
        uint32_t hp1; CVTPK(hp1, b0v, b1v);
        lx = b0v - __uint_as_float(hp1 << 16);
        ly = b1v - __uint_as_float(hp1 & 0xFFFF0000u);
        uint32_t lp1; CVTPK(lp1, lx, ly);
        *(uint32_t*)(cth + o1 + col) = hp1;
        *(uint32_t*)(ctl + o1 + col) = lp1;
    }
}

// ---------------------------------------------------------------------------
extern "C" void kernel_launch(void* const* d_in, const int* in_sizes, int n_in,
                              void* d_out, int out_size)
{
    const float* x     = (const float*)d_in[0];
    const float* Wq    = (const float*)d_in[1];
    const float* Wk    = (const float*)d_in[2];
    const float* Wv    = (const float*)d_in[3];
    const float* Wo    = (const float*)d_in[4];
    const float* log_c = (const float*)d_in[5];
    const float* log_b = (const float*)d_in[6];
    float* out = (float*)d_out;

    float *qptr, *kptr, *vptr, *knp, *qnp;
    cudaGetSymbolAddress((void**)&qptr, g_q);
    cudaGetSymbolAddress((void**)&kptr, g_k);
    cudaGetSymbolAddress((void**)&vptr, g_v);
    cudaGetSymbolAddress((void**)&knp,  g_kn);
    cudaGetSymbolAddress((void**)&qnp,  g_qn);

    __nv_bfloat16 *xh, *xl, *wqh, *wql, *wkh, *wkl, *wvh, *wvl, *woh, *wol, *cth, *ctl;
    __nv_bfloat16 *qh, *ql, *kh, *kl, *vh, *vl;
    cudaGetSymbolAddress((void**)&xh,  g_xh);  cudaGetSymbolAddress((void**)&xl,  g_xl);
    cudaGetSymbolAddress((void**)&wqh, g_wqh); cudaGetSymbolAddress((void**)&wql, g_wql);
    cudaGetSymbolAddress((void**)&wkh, g_wkh); cudaGetSymbolAddress((void**)&wkl, g_wkl);
    cudaGetSymbolAddress((void**)&wvh, g_wvh); cudaGetSymbolAddress((void**)&wvl, g_wvl);
    cudaGetSymbolAddress((void**)&woh, g_woh); cudaGetSymbolAddress((void**)&wol, g_wol);
    cudaGetSymbolAddress((void**)&cth, g_cth); cudaGetSymbolAddress((void**)&ctl, g_ctl);
    cudaGetSymbolAddress((void**)&qh,  g_qh);  cudaGetSymbolAddress((void**)&ql,  g_ql);
    cudaGetSymbolAddress((void**)&kh,  g_kh);  cudaGetSymbolAddress((void**)&kl,  g_kl);
    cudaGetSymbolAddress((void**)&vh,  g_vh);  cudaGetSymbolAddress((void**)&vl,  g_vl);

    cudaFuncSetAttribute(gemm_tc, cudaFuncAttributeMaxDynamicSharedMemorySize, GEMM_SMEM);
    cudaFuncSetAttribute(hyp_attn_mma, cudaFuncAttributeMaxDynamicSharedMemorySize, ATT_SMEM);

    // Split inputs to bf16 hi/lo
    const int n4x = ROWS_ * D_ / 4;
    const int n4w = D_ * D_ / 4;
    split_bf16<<<n4x / 256, 256>>>(x,  xh,  xl,  n4x);
    split_bf16<<<n4w / 256, 256>>>(Wq, wqh, wql, n4w);
    split_bf16<<<n4w / 256, 256>>>(Wk, wkh, wkl, n4w);
    split_bf16<<<n4w / 256, 256>>>(Wv, wvh, wvl, n4w);
    split_bf16<<<n4w / 256, 256>>>(Wo, woh, wol, n4w);

    // QKV projections via HMMA, fused hi/lo split epilogue
    gemm_tc<<<dim3(D_ / 64, ROWS_ / 128, 3), 256, GEMM_SMEM>>>(
        xh, xl, wqh, wql, wkh, wkl, wvh, wvl, qptr, kptr, vptr,
        qh, ql, kh, kl, vh, vl, 1);

    // Norms
    row_norms<<<BHN_ / 8, 256>>>(qptr, qnp);
    row_norms<<<BHN_ / 8, 256>>>(kptr, knp);

    // Tensor-core attention: 128-row q-tiles, 8 warps
    hyp_attn_mma<<<dim3(16, 32), 256, ATT_SMEM>>>(qh, ql, kh, kl, vh, vl,
                                                  qnp, knp, cth, ctl, log_c, log_b);

    // Output projection (fp32 out only)
    gemm_tc<<<dim3(D_ / 64, ROWS_ / 128, 1), 256, GEMM_SMEM>>>(
        cth, ctl, woh, wol, woh, wol, woh, wol, out, out, out,
        (__nv_bfloat16*)nullptr, (__nv_bfloat16*)nullptr,
        (__nv_bfloat16*)nullptr, (__nv_bfloat16*)nullptr,
        (__nv_bfloat16*)nullptr, (__nv_bfloat16*)nullptr, 0);
}